// round 15
// baseline (speedup 1.0000x reference)
#include <cuda_runtime.h>
#include <cstdint>

// Problem constants (fixed by the reference: B=8, H=16, L=512, D=64)
#define BH   128
#define LSEQ 512
#define DH   64
#define TQ   64     // q rows per block
#define TK   64     // k/v tile cols/rows
#define NTHR 512
#define NSTEPS 10

#define QS_STRIDE  68           // %32==4 -> conflict-free fragment rows
#define S_STRIDE   516          // %32==4
// smem floats: Qs 64*68 | Kb 2*64*68 | Vb 2*64*68 | S 64*516 | Rinv 64
#define OFF_KB   (TQ * QS_STRIDE)
#define OFF_VB   (OFF_KB + 2 * TK * QS_STRIDE)
#define OFF_S    (OFF_VB + 2 * TK * QS_STRIDE)
#define OFF_RINV (OFF_S + TQ * S_STRIDE)
#define SMEM_FLOATS (OFF_RINV + TQ)
#define SMEM_BYTES  (SMEM_FLOATS * sizeof(float))   // ~219 KB -> 1 CTA/SM

__device__ __forceinline__ uint32_t f2tf(float x) {
    uint32_t r;
    asm("cvt.rna.tf32.f32 %0, %1;" : "=r"(r) : "f"(x));
    return r;
}
__device__ __forceinline__ uint32_t f2tf_bits(uint32_t xb) {
    uint32_t r;
    asm("cvt.rna.tf32.f32 %0, %1;" : "=r"(r) : "f"(__uint_as_float(xb)));
    return r;
}

__device__ __forceinline__ void mma_tf32(float d[4], const uint32_t a[4], const uint32_t b[2]) {
    asm volatile(
        "mma.sync.aligned.m16n8k8.row.col.f32.tf32.tf32.f32 "
        "{%0,%1,%2,%3}, {%4,%5,%6,%7}, {%8,%9}, {%0,%1,%2,%3};\n"
        : "+f"(d[0]), "+f"(d[1]), "+f"(d[2]), "+f"(d[3])
        : "r"(a[0]), "r"(a[1]), "r"(a[2]), "r"(a[3]), "r"(b[0]), "r"(b[1]));
}

// ldmatrix x4 on 32-bit data (fragment mapping verified on-chip in round 7)
__device__ __forceinline__ void ldsm_x4(uint32_t& r0, uint32_t& r1,
                                        uint32_t& r2, uint32_t& r3, uint32_t addr) {
    asm volatile("ldmatrix.sync.aligned.m8n8.x4.shared.b16 {%0,%1,%2,%3}, [%4];"
                 : "=r"(r0), "=r"(r1), "=r"(r2), "=r"(r3) : "r"(addr));
}

__device__ __forceinline__ void cp_async16(void* smem_ptr, const void* gptr) {
    uint32_t s = (uint32_t)__cvta_generic_to_shared(smem_ptr);
    asm volatile("cp.async.cg.shared.global [%0], [%1], 16;" :: "r"(s), "l"(gptr));
}
#define CP_COMMIT()  asm volatile("cp.async.commit_group;")
#define CP_WAIT0()   asm volatile("cp.async.wait_group 0;")

__global__ __launch_bounds__(NTHR, 1)
void attn_fused_kernel(const float* __restrict__ q,
                       const float* __restrict__ k,
                       const float* __restrict__ v,
                       const float* __restrict__ sel,
                       const int* __restrict__ mask,
                       float* __restrict__ ctx,
                       float* __restrict__ attn)
{
    extern __shared__ float sm[];
    float (*Qs)[QS_STRIDE]    = (float (*)[QS_STRIDE])sm;                 // [64][68]
    float (*Kb)[TK][QS_STRIDE]= (float (*)[TK][QS_STRIDE])(sm + OFF_KB);  // [2][64][68]
    float (*Vb)[TK][QS_STRIDE]= (float (*)[TK][QS_STRIDE])(sm + OFF_VB);  // [2][64][68]
    float (*S)[S_STRIDE]      = (float (*)[S_STRIDE])(sm + OFF_S);        // [64][516]
    float* Rinv               = sm + OFF_RINV;                            // [64]

    const int bh  = blockIdx.y;
    const int qt  = blockIdx.x;
    const int tid = threadIdx.x;
    const int warp = tid >> 5, lane = tid & 31;
    const int g  = lane >> 2;          // fragment group 0..7
    const int t  = lane & 3;           // fragment thread-in-group 0..3

    const float* qg = q + ((size_t)bh * LSEQ + (size_t)qt * TQ) * DH;
    const float* kg = k + (size_t)bh * LSEQ * DH;
    const float* vg = v + (size_t)bh * LSEQ * DH;

    const size_t base = (size_t)bh * LSEQ * LSEQ + (size_t)qt * TQ * LSEQ;
    const float* selp = sel + base;
    const int* mp = mask + base;
    float* attnp = attn + base;

    // shared-address bases for ldmatrix
    const uint32_t smem_u32 = (uint32_t)__cvta_generic_to_shared(sm);
    const uint32_t kb_u32   = smem_u32 + OFF_KB * 4;
    const uint32_t s_u32    = smem_u32 + OFF_S * 4;

    // A-group geometry (meaningful for warps 0..7)
    const int wm = warp & 3;           // rows wm*16..+15
    const int wn = (warp >> 2) & 1;    // cols wn*32..+31
    const uint32_t boff = (uint32_t)(((wn * 32 + (lane & 7)) * QS_STRIDE + 4 * (lane >> 3)) * 4);
    const uint32_t aoff = (uint32_t)(((wm * 16 + (lane & 15)) * S_STRIDE + 4 * (lane >> 4)) * 4);

    // ---- prologue: async load Q tile + K tile 0 (all threads) ----
    #pragma unroll
    for (int i = tid; i < TQ * DH / 4; i += NTHR) {
        int e = i * 4, r = e >> 6, c = e & 63;
        cp_async16(&Qs[r][c], qg + e);
        cp_async16(&Kb[0][r][c], kg + e);
    }
    CP_COMMIT();
    CP_WAIT0();
    __syncthreads();

    // ---- Q tf32 fragments with folded scale (A warps only use them) ----
    uint32_t qa[DH / 8][4];
    if (warp < 8) {
        #pragma unroll
        for (int ks = 0; ks < DH / 8; ++ks) {
            const int k0 = ks * 8;
            qa[ks][0] = f2tf(0.125f * Qs[wm * 16 + g    ][k0 + t    ]);
            qa[ks][1] = f2tf(0.125f * Qs[wm * 16 + g + 8][k0 + t    ]);
            qa[ks][2] = f2tf(0.125f * Qs[wm * 16 + g    ][k0 + t + 4]);
            qa[ks][3] = f2tf(0.125f * Qs[wm * 16 + g + 8][k0 + t + 4]);
        }
    }

    float accPV[4][4];                 // persistent PV accumulators (A)
    #pragma unroll
    for (int nt = 0; nt < 4; ++nt)
        #pragma unroll
        for (int j = 0; j < 4; ++j) accPV[nt][j] = 0.f;

    float rs[8];                       // row sums (B)
    #pragma unroll
    for (int j = 0; j < 8; ++j) rs[j] = 0.f;

    // =====================================================================
    // 10-step lockstep pipeline:
    //   step s: A: prefetch K(s+1); QK(s) -> S; PV(s-2) on E
    //           B: prefetch V(s-1); E(s-1) = exp(raw + sel), masked -> 0;
    //              s==8: Rinv; s==9: write attn rows 0..47
    // =====================================================================
    for (int s = 0; s < NSTEPS; ++s) {
        if (warp < 8) {
            // ---- group A ----
            if (s <= 6) {
                const float* kn = kg + (size_t)(s + 1) * TK * DH;
                #pragma unroll
                for (int i = tid; i < TK * DH / 4; i += 256) {
                    int e = i * 4, r = e >> 6, c = e & 63;
                    cp_async16(&Kb[(s + 1) & 1][r][c], kn + e);
                }
                CP_COMMIT();
            }
            if (s <= 7) {
                // QK(s): raw scores into S cols [s*64, s*64+64)
                const uint32_t kbase = kb_u32 + (uint32_t)((s & 1) * TK * QS_STRIDE * 4) + boff;
                float acc[4][4];
                #pragma unroll
                for (int nt = 0; nt < 4; ++nt)
                    #pragma unroll
                    for (int j = 0; j < 4; ++j) acc[nt][j] = 0.f;
                #pragma unroll
                for (int kb = 0; kb < 4; ++kb) {
                    #pragma unroll
                    for (int nt = 0; nt < 4; ++nt) {
                        uint32_t b0, b1, b2, b3;
                        ldsm_x4(b0, b1, b2, b3,
                                kbase + (uint32_t)((nt * 8 * QS_STRIDE + kb * 16) * 4));
                        uint32_t blo[2] = {f2tf_bits(b0), f2tf_bits(b1)};
                        uint32_t bhi[2] = {f2tf_bits(b2), f2tf_bits(b3)};
                        mma_tf32(acc[nt], qa[2 * kb    ], blo);
                        mma_tf32(acc[nt], qa[2 * kb + 1], bhi);
                    }
                }
                #pragma unroll
                for (int nt = 0; nt < 4; ++nt) {
                    const int n0 = s * TK + wn * 32 + nt * 8 + 2 * t;
                    *(float2*)&S[wm * 16 + g    ][n0] = make_float2(acc[nt][0], acc[nt][1]);
                    *(float2*)&S[wm * 16 + g + 8][n0] = make_float2(acc[nt][2], acc[nt][3]);
                }
            }
            if (s >= 2) {
                // PV(vt = s-2): accumulate E @ V
                const int vt = s - 2;
                float (*Vs)[QS_STRIDE] = Vb[vt & 1];
                #pragma unroll
                for (int ks = 0; ks < TK / 8; ++ks) {
                    const int sk = vt * TK + ks * 8;
                    const int vk = ks * 8;
                    uint32_t a[4];
                    ldsm_x4(a[0], a[1], a[2], a[3], s_u32 + aoff + (uint32_t)(sk * 4));
                    a[0] = f2tf_bits(a[0]); a[1] = f2tf_bits(a[1]);
                    a[2] = f2tf_bits(a[2]); a[3] = f2tf_bits(a[3]);
                    #pragma unroll
                    for (int nt = 0; nt < 4; ++nt) {
                        const int n0 = wn * 32 + nt * 8;
                        uint32_t b[2];
                        b[0] = f2tf(Vs[vk + t    ][n0 + g]);
                        b[1] = f2tf(Vs[vk + t + 4][n0 + g]);
                        mma_tf32(accPV[nt], a, b);
                    }
                }
            }
        } else {
            // ---- group B ----
            if (s >= 1 && s <= 8) {
                const int kt = s - 1;
                // prefetch V(kt) for PV(kt) at step kt+2
                const float* vn = vg + (size_t)kt * TK * DH;
                #pragma unroll
                for (int i = tid - 256; i < TK * DH / 4; i += 256) {
                    int e = i * 4, r = e >> 6, c = e & 63;
                    cp_async16(&Vb[kt & 1][r][c], vn + e);
                }
                CP_COMMIT();

                // E(kt) = exp(raw + sel), masked -> 0; accumulate row sums
                const int bw = warp - 8;
                const int c = kt * TK + lane * 2;
                #pragma unroll
                for (int j = 0; j < 8; ++j) {
                    const int r = bw * 8 + j;
                    float2 sv = *(float2*)&S[r][c];
                    float2 se = *(const float2*)&selp[(size_t)r * LSEQ + c];
                    int2   mv = *(const int2*)  &mp  [(size_t)r * LSEQ + c];
                    float e0 = mv.x ? __expf(sv.x + se.x) : 0.f;
                    float e1 = mv.y ? __expf(sv.y + se.y) : 0.f;
                    *(float2*)&S[r][c] = make_float2(e0, e1);
                    rs[j] += e0 + e1;
                }
                if (s == 8) {
                    #pragma unroll
                    for (int j = 0; j < 8; ++j) {
                        float ss = rs[j];
                        #pragma unroll
                        for (int o = 16; o > 0; o >>= 1)
                            ss += __shfl_xor_sync(0xffffffffu, ss, o);
                        if (lane == 0) Rinv[bw * 8 + j] = 1.0f / ss;
                    }
                }
            }
            if (s == 9) {
                // write attn rows 0..47 (overlaps A's PV7)
                const int bw = warp - 8;
                #pragma unroll
                for (int j = 0; j < 6; ++j) {
                    const int r = bw * 6 + j;
                    const float inv = Rinv[r];
                    #pragma unroll
                    for (int i = 0; i < 4; ++i) {
                        const int c = i * 128 + lane * 4;
                        float4 e4 = *(const float4*)&S[r][c];
                        float4 a4;
                        a4.x = e4.x * inv; a4.y = e4.y * inv;
                        a4.z = e4.z * inv; a4.w = e4.w * inv;
                        *(float4*)&attnp[(size_t)r * LSEQ + c] = a4;
                    }
                }
            }
        }
        CP_WAIT0();
        __syncthreads();
    }

    // ---- epilogue (A warps): ctx = accPV * inv, then attn rows 48..63 ----
    if (warp < 8) {
        const int r0 = wm * 16 + g;
        const int r1 = r0 + 8;
        const float inv0 = Rinv[r0];
        const float inv1 = Rinv[r1];
        float* cp = ctx + ((size_t)bh * LSEQ + (size_t)qt * TQ) * DH;
        #pragma unroll
        for (int nt = 0; nt < 4; ++nt) {
            const int n0 = wn * 32 + nt * 8 + 2 * t;
            *(float2*)&cp[(size_t)r0 * DH + n0] =
                make_float2(accPV[nt][0] * inv0, accPV[nt][1] * inv0);
            *(float2*)&cp[(size_t)r1 * DH + n0] =
                make_float2(accPV[nt][2] * inv1, accPV[nt][3] * inv1);
        }
        // attn rows 48..63: warp w -> rows 48 + 2w, 48 + 2w + 1
        #pragma unroll
        for (int j = 0; j < 2; ++j) {
            const int r = 48 + warp * 2 + j;
            const float inv = Rinv[r];
            #pragma unroll
            for (int i = 0; i < 4; ++i) {
                const int c = i * 128 + lane * 4;
                float4 e4 = *(const float4*)&S[r][c];
                float4 a4;
                a4.x = e4.x * inv; a4.y = e4.y * inv;
                a4.z = e4.z * inv; a4.w = e4.w * inv;
                *(float4*)&attnp[(size_t)r * LSEQ + c] = a4;
            }
        }
    }
}

extern "C" void kernel_launch(void* const* d_in, const int* in_sizes, int n_in,
                              void* d_out, int out_size)
{
    (void)in_sizes; (void)n_in; (void)out_size;
    const float* q = (const float*)d_in[0];
    const float* k = (const float*)d_in[1];
    const float* v = (const float*)d_in[2];
    const float* sel = (const float*)d_in[3];
    const int* mask = (const int*)d_in[4];

    float* ctx  = (float*)d_out;                          // [128,512,64]
    float* attn = ctx + (size_t)BH * LSEQ * DH;           // [128,512,512]

    cudaFuncSetAttribute(attn_fused_kernel,
                         cudaFuncAttributeMaxDynamicSharedMemorySize, (int)SMEM_BYTES);

    dim3 grid(LSEQ / TQ, BH);   // (8, 128) = 1024 blocks
    attn_fused_kernel<<<grid, NTHR, SMEM_BYTES>>>(q, k, v, sel, mask, ctx, attn);
}

// round 16
// speedup vs baseline: 1.3927x; 1.3927x over previous
#include <cuda_runtime.h>
#include <cstdint>

// Problem constants (fixed by the reference: B=8, H=16, L=512, D=64)
#define BH   128
#define LSEQ 512
#define DH   64
#define TQ   64     // q rows per block
#define TK   64     // k/v tile cols/rows
#define NTHR 512

#define QS_STRIDE  68           // %32==4 -> conflict-free fragment rows
#define S_STRIDE   516          // %32==4
#define SMEM_FLOATS (TQ * QS_STRIDE + 2 * TK * QS_STRIDE + TQ * S_STRIDE + 2 * TQ)
#define SMEM_BYTES  (SMEM_FLOATS * sizeof(float))

__device__ __forceinline__ uint32_t f2tf(float x) {
    uint32_t r;
    asm("cvt.rna.tf32.f32 %0, %1;" : "=r"(r) : "f"(x));
    return r;
}
__device__ __forceinline__ uint32_t f2tf_bits(uint32_t xb) {
    uint32_t r;
    asm("cvt.rna.tf32.f32 %0, %1;" : "=r"(r) : "f"(__uint_as_float(xb)));
    return r;
}

__device__ __forceinline__ void mma_tf32(float d[4], const uint32_t a[4], const uint32_t b[2]) {
    asm volatile(
        "mma.sync.aligned.m16n8k8.row.col.f32.tf32.tf32.f32 "
        "{%0,%1,%2,%3}, {%4,%5,%6,%7}, {%8,%9}, {%0,%1,%2,%3};\n"
        : "+f"(d[0]), "+f"(d[1]), "+f"(d[2]), "+f"(d[3])
        : "r"(a[0]), "r"(a[1]), "r"(a[2]), "r"(a[3]), "r"(b[0]), "r"(b[1]));
}

// ldmatrix x4 on 32-bit data (fragment mapping verified on-chip in round 7)
__device__ __forceinline__ void ldsm_x4(uint32_t& r0, uint32_t& r1,
                                        uint32_t& r2, uint32_t& r3, uint32_t addr) {
    asm volatile("ldmatrix.sync.aligned.m8n8.x4.shared.b16 {%0,%1,%2,%3}, [%4];"
                 : "=r"(r0), "=r"(r1), "=r"(r2), "=r"(r3) : "r"(addr));
}

__device__ __forceinline__ void cp_async16(void* smem_ptr, const void* gptr) {
    uint32_t s = (uint32_t)__cvta_generic_to_shared(smem_ptr);
    asm volatile("cp.async.cg.shared.global [%0], [%1], 16;" :: "r"(s), "l"(gptr));
}
#define CP_COMMIT()  asm volatile("cp.async.commit_group;")
#define CP_WAIT0()   asm volatile("cp.async.wait_group 0;")

// named barriers: producer arrives, consumer syncs
#define BAR_ARRIVE(id)  asm volatile("bar.arrive %0, 512;" :: "r"(id))
#define BAR_SYNC(id)    asm volatile("bar.sync %0, 512;" :: "r"(id) : "memory")
#define BAR_A_GROUP()   asm volatile("bar.sync 9, 256;" ::: "memory")
#define MEMBAR_CTA()    asm volatile("membar.cta;" ::: "memory")

__global__ __launch_bounds__(NTHR, 1)
void attn_fused_kernel(const float* __restrict__ q,
                       const float* __restrict__ k,
                       const float* __restrict__ v,
                       const float* __restrict__ sel,
                       const int* __restrict__ mask,
                       float* __restrict__ ctx,
                       float* __restrict__ attn)
{
    extern __shared__ float sm[];
    float (*Qs)[QS_STRIDE]    = (float (*)[QS_STRIDE])sm;                         // [64][68]
    float (*KV)[TK][QS_STRIDE]= (float (*)[TK][QS_STRIDE])(sm + TQ * QS_STRIDE);  // [2][64][68]
    float (*S)[S_STRIDE]      = (float (*)[S_STRIDE])(sm + TQ * QS_STRIDE + 2 * TK * QS_STRIDE); // [64][516]
    float* Rmax               = sm + TQ * QS_STRIDE + 2 * TK * QS_STRIDE + TQ * S_STRIDE;        // [64]
    float* Rinv               = Rmax + TQ;                                                        // [64]

    const int bh  = blockIdx.y;
    const int qt  = blockIdx.x;
    const int tid = threadIdx.x;
    const int warp = tid >> 5, lane = tid & 31;
    const int g  = lane >> 2;          // fragment group 0..7
    const int t  = lane & 3;           // fragment thread-in-group 0..3

    const float* qg = q + ((size_t)bh * LSEQ + (size_t)qt * TQ) * DH;
    const float* kg = k + (size_t)bh * LSEQ * DH;
    const float* vg = v + (size_t)bh * LSEQ * DH;

    const size_t base = (size_t)bh * LSEQ * LSEQ + (size_t)qt * TQ * LSEQ;
    const float* selp = sel + base;
    const int* mp = mask + base;
    float* attnp = attn + base;

    // shared-address bases for ldmatrix
    const uint32_t smem_u32 = (uint32_t)__cvta_generic_to_shared(sm);
    const uint32_t kv_u32   = smem_u32 + TQ * QS_STRIDE * 4;
    const uint32_t s_u32    = smem_u32 + (TQ * QS_STRIDE + 2 * TK * QS_STRIDE) * 4;

    // ---- prologue: async load Q tile + K tile 0 (all threads) ----
    #pragma unroll
    for (int i = tid; i < TQ * DH / 4; i += NTHR) {
        int e = i * 4, r = e >> 6, c = e & 63;
        cp_async16(&Qs[r][c], qg + e);
        cp_async16(&KV[0][r][c], kg + e);
    }
    CP_COMMIT();
    CP_WAIT0();
    __syncthreads();

    // =====================================================================
    // phase 1 (warp-specialized): A = warps 0..7 compute raw S = (Q*s)@K^T;
    //                             B = warps 8..15 stream sel/mask, finish S.
    // A never waits on B (bar.arrive only); B prefetches its global loads
    // into registers BEFORE the bar.sync so DRAM latency overlaps the wait.
    // =====================================================================
    if (warp < 8) {
        // ---- group A: GEMM producer ----
        const int wm = warp & 3;           // rows wm*16..+15
        const int wn = warp >> 2;          // cols wn*32..+31 (4 nt sub-tiles)
        const int atid = tid;              // 0..255
        const uint32_t boff = (uint32_t)(((wn * 32 + (lane & 7)) * QS_STRIDE + 4 * (lane >> 3)) * 4);

        uint32_t qa[DH / 8][4];
        #pragma unroll
        for (int ks = 0; ks < DH / 8; ++ks) {
            const int k0 = ks * 8;
            qa[ks][0] = f2tf(0.125f * Qs[wm * 16 + g    ][k0 + t    ]);
            qa[ks][1] = f2tf(0.125f * Qs[wm * 16 + g + 8][k0 + t    ]);
            qa[ks][2] = f2tf(0.125f * Qs[wm * 16 + g    ][k0 + t + 4]);
            qa[ks][3] = f2tf(0.125f * Qs[wm * 16 + g + 8][k0 + t + 4]);
        }

        for (int kt = 0; kt < LSEQ / TK; ++kt) {
            if (kt > 0) {
                CP_WAIT0();
                BAR_A_GROUP();
            }
            if (kt + 1 < LSEQ / TK) {
                const float* kn = kg + (size_t)(kt + 1) * TK * DH;
                #pragma unroll
                for (int i = atid; i < TK * DH / 4; i += 256) {
                    int e = i * 4, r = e >> 6, c = e & 63;
                    cp_async16(&KV[(kt + 1) & 1][r][c], kn + e);
                }
                CP_COMMIT();
            }

            const uint32_t kbase = kv_u32 + (uint32_t)((kt & 1) * TK * QS_STRIDE * 4) + boff;
            float acc[4][4];
            #pragma unroll
            for (int nt = 0; nt < 4; ++nt)
                #pragma unroll
                for (int j = 0; j < 4; ++j) acc[nt][j] = 0.f;

            #pragma unroll
            for (int kb = 0; kb < 4; ++kb) {
                #pragma unroll
                for (int nt = 0; nt < 4; ++nt) {
                    uint32_t b0, b1, b2, b3;
                    ldsm_x4(b0, b1, b2, b3,
                            kbase + (uint32_t)((nt * 8 * QS_STRIDE + kb * 16) * 4));
                    uint32_t blo[2] = {f2tf_bits(b0), f2tf_bits(b1)};
                    uint32_t bhi[2] = {f2tf_bits(b2), f2tf_bits(b3)};
                    mma_tf32(acc[nt], qa[2 * kb    ], blo);
                    mma_tf32(acc[nt], qa[2 * kb + 1], bhi);
                }
            }

            #pragma unroll
            for (int nt = 0; nt < 4; ++nt) {
                const int n0 = kt * TK + wn * 32 + nt * 8 + 2 * t;
                *(float2*)&S[wm * 16 + g    ][n0] = make_float2(acc[nt][0], acc[nt][1]);
                *(float2*)&S[wm * 16 + g + 8][n0] = make_float2(acc[nt][2], acc[nt][3]);
            }
            MEMBAR_CTA();           // make STS visible before signaling B
            BAR_ARRIVE(1 + kt);     // tile kt ready for group B
        }

        // prefetch V tile 0 into buf 0 (overlaps B's tail + exp pass)
        #pragma unroll
        for (int i = atid; i < TK * DH / 4; i += 256) {
            int e = i * 4, r = e >> 6, c = e & 63;
            cp_async16(&KV[0][r][c], vg + e);
        }
        CP_COMMIT();
    } else {
        // ---- group B: sel/mask streamer + masking consumer ----
        // LDGs for tile kt issue BEFORE bar.sync(1+kt): latency hides under
        // the wait for A instead of following it.
        const int bw = warp - 8;           // 0..7 -> rows bw*8..+7
        float m[8];
        #pragma unroll
        for (int j = 0; j < 8; ++j) m[j] = -1e30f;

        for (int kt = 0; kt < LSEQ / TK; ++kt) {
            const int c = kt * TK + lane * 2;
            float2 se[8];
            int2   mv[8];
            #pragma unroll
            for (int j = 0; j < 8; ++j) {
                const int r = bw * 8 + j;
                se[j] = *(const float2*)&selp[(size_t)r * LSEQ + c];
                mv[j] = *(const int2*)  &mp  [(size_t)r * LSEQ + c];
            }
            BAR_SYNC(1 + kt);              // loads in flight while waiting for A
            #pragma unroll
            for (int j = 0; j < 8; ++j) {
                const int r = bw * 8 + j;
                float2 sv = *(float2*)&S[r][c];
                float x0 = mv[j].x ? sv.x + se[j].x : -1e12f;
                float x1 = mv[j].y ? sv.y + se[j].y : -1e12f;
                *(float2*)&S[r][c] = make_float2(x0, x1);
                m[j] = fmaxf(m[j], fmaxf(x0, x1));
            }
        }
        // warp-reduce row maxima, write Rmax
        #pragma unroll
        for (int j = 0; j < 8; ++j) {
            float mm = m[j];
            #pragma unroll
            for (int o = 16; o > 0; o >>= 1)
                mm = fmaxf(mm, __shfl_xor_sync(0xffffffffu, mm, o));
            if (lane == 0) Rmax[bw * 8 + j] = mm;
        }
    }
    __syncthreads();   // S (masked+biased) + Rmax complete; V tile0 in flight

    // ---- phase 2a (all warps): E = exp(x - max) into S (fp32), Rinv = 1/sum ----
    #pragma unroll
    for (int rr = 0; rr < 4; ++rr) {
        const int r = warp * 4 + rr;
        const float lmax = Rmax[r];
        float lsum = 0.f;
        #pragma unroll
        for (int i = 0; i < 4; ++i) {
            const int c = i * 128 + lane * 4;
            float4 sv = *(const float4*)&S[r][c];
            float4 e4;
            e4.x = __expf(sv.x - lmax);
            e4.y = __expf(sv.y - lmax);
            e4.z = __expf(sv.z - lmax);
            e4.w = __expf(sv.w - lmax);
            *(float4*)&S[r][c] = e4;
            lsum += (e4.x + e4.y) + (e4.z + e4.w);
        }
        #pragma unroll
        for (int o = 16; o > 0; o >>= 1)
            lsum += __shfl_xor_sync(0xffffffffu, lsum, o);
        if (lane == 0) Rinv[r] = 1.0f / lsum;
    }
    __syncthreads();   // E + Rinv visible to both groups

    // =====================================================================
    // phase 2b (warp-specialized): A = warps 0..7 PV GEMM (scale by Rinv at
    // the end); B = warps 8..15 stream attn = E * inv to global.
    // =====================================================================
    if (warp < 8) {
        // ---- group A: ctx = (E @ V) * inv ----
        const int wm = warp & 3;
        const int wn = warp >> 2;          // 2 groups x 32 cols
        const int atid = tid;              // 0..255
        const uint32_t aoff = (uint32_t)(((wm * 16 + (lane & 15)) * S_STRIDE + 4 * (lane >> 4)) * 4);

        float acc[4][4];
        #pragma unroll
        for (int nt = 0; nt < 4; ++nt)
            #pragma unroll
            for (int j = 0; j < 4; ++j) acc[nt][j] = 0.f;

        for (int vt = 0; vt < LSEQ / TK; ++vt) {
            CP_WAIT0();
            BAR_A_GROUP();
            if (vt + 1 < LSEQ / TK) {
                const float* vn = vg + (size_t)(vt + 1) * TK * DH;
                #pragma unroll
                for (int i = atid; i < TK * DH / 4; i += 256) {
                    int e = i * 4, r = e >> 6, c = e & 63;
                    cp_async16(&KV[(vt + 1) & 1][r][c], vn + e);
                }
                CP_COMMIT();
            }

            float (*Vs)[QS_STRIDE] = KV[vt & 1];
            #pragma unroll
            for (int ks = 0; ks < TK / 8; ++ks) {
                const int sk = vt * TK + ks * 8;   // S column (k index)
                const int vk = ks * 8;             // V smem row
                uint32_t a[4];                     // E fp32 -> cvt in regs
                ldsm_x4(a[0], a[1], a[2], a[3], s_u32 + aoff + (uint32_t)(sk * 4));
                a[0] = f2tf_bits(a[0]); a[1] = f2tf_bits(a[1]);
                a[2] = f2tf_bits(a[2]); a[3] = f2tf_bits(a[3]);
                #pragma unroll
                for (int nt = 0; nt < 4; ++nt) {
                    const int n0 = wn * 32 + nt * 8;
                    uint32_t b[2];
                    b[0] = f2tf(Vs[vk + t    ][n0 + g]);
                    b[1] = f2tf(Vs[vk + t + 4][n0 + g]);
                    mma_tf32(acc[nt], a, b);
                }
            }
            BAR_A_GROUP();   // buf[vt&1] free for prefetch at vt+1
        }

        const int r0 = wm * 16 + g;
        const int r1 = r0 + 8;
        const float inv0 = Rinv[r0];
        const float inv1 = Rinv[r1];
        float* cp = ctx + ((size_t)bh * LSEQ + (size_t)qt * TQ) * DH;
        #pragma unroll
        for (int nt = 0; nt < 4; ++nt) {
            const int n0 = wn * 32 + nt * 8 + 2 * t;
            *(float2*)&cp[(size_t)r0 * DH + n0] =
                make_float2(acc[nt][0] * inv0, acc[nt][1] * inv0);
            *(float2*)&cp[(size_t)r1 * DH + n0] =
                make_float2(acc[nt][2] * inv1, acc[nt][3] * inv1);
        }
    } else {
        // ---- group B: attn = E * inv, coalesced float4 stream ----
        const int bw = warp - 8;           // 0..7 -> rows bw*8..+7
        #pragma unroll
        for (int j = 0; j < 8; ++j) {
            const int r = bw * 8 + j;
            const float inv = Rinv[r];
            #pragma unroll
            for (int i = 0; i < 4; ++i) {
                const int c = i * 128 + lane * 4;
                float4 e4 = *(const float4*)&S[r][c];
                float4 a4;
                a4.x = e4.x * inv;
                a4.y = e4.y * inv;
                a4.z = e4.z * inv;
                a4.w = e4.w * inv;
                *(float4*)&attnp[(size_t)r * LSEQ + c] = a4;
            }
        }
    }
}

extern "C" void kernel_launch(void* const* d_in, const int* in_sizes, int n_in,
                              void* d_out, int out_size)
{
    (void)in_sizes; (void)n_in; (void)out_size;
    const float* q = (const float*)d_in[0];
    const float* k = (const float*)d_in[1];
    const float* v = (const float*)d_in[2];
    const float* sel = (const float*)d_in[3];
    const int* mask = (const int*)d_in[4];

    float* ctx  = (float*)d_out;                          // [128,512,64]
    float* attn = ctx + (size_t)BH * LSEQ * DH;           // [128,512,512]

    cudaFuncSetAttribute(attn_fused_kernel,
                         cudaFuncAttributeMaxDynamicSharedMemorySize, (int)SMEM_BYTES);

    dim3 grid(LSEQ / TQ, BH);   // (8, 128) = 1024 blocks
    attn_fused_kernel<<<grid, NTHR, SMEM_BYTES>>>(q, k, v, sel, mask, ctx, attn);
}